// round 3
// baseline (speedup 1.0000x reference)
#include <cuda_runtime.h>
#include <cuda_bf16.h>

// Problem constants
#define BB 8
#define NN 2048
#define KNN 16
#define NPTS (BB * NN)            // 16384
#define NEDGE (NPTS * KNN)        // 262144

// Static scratch (allocation-free rule): ~1.03 GB total
__device__ float g_X0[NPTS * 256];
__device__ float g_X1[NPTS * 256];
__device__ float g_sqn[NPTS];
__device__ float g_S[(long long)BB * NN * NN];     // 134 MB distance scores
__device__ int   g_idx[NEDGE];
__device__ float g_P[NPTS * 512];
__device__ float g_Q[NPTS * 512];
__device__ float g_Wd[512 * 512];
__device__ float g_H1[(long long)NEDGE * 512];     // 536 MB
__device__ float g_H2[(long long)NEDGE * 256];     // 268 MB

// ---------------------------------------------------------------------------
// Generic 64x64 register-tiled SGEMM.
// epi: 0 = (+bias if bias!=null), 1 = bias+relu, 2 = dist: C = -2*acc + sqn[n]
// transB: 0 -> B[k*ldb+n], 1 -> B[n*ldb+k]
// Batched via blockIdx.z with element strides sA/sB/sC/sSqn.
// ---------------------------------------------------------------------------
__global__ __launch_bounds__(256)
void sgemm64(const float* __restrict__ A, const float* __restrict__ B,
             const float* __restrict__ bias, const float* __restrict__ sqn,
             float* __restrict__ C,
             int M, int Nn, int Kd,
             int lda, int ldb, int ldc,
             int transB, int epi,
             long long sA, long long sB, long long sC, int sSqn)
{
    int bz = blockIdx.z;
    A += bz * sA;
    B += bz * sB;
    C += bz * sC;
    const float* sq = sqn ? (sqn + (long long)bz * sSqn) : nullptr;

    __shared__ float As[16][68];
    __shared__ float Bs[16][68];

    int t = threadIdx.x;
    int tx = t & 15, ty = t >> 4;
    int bm = blockIdx.y * 64, bn = blockIdx.x * 64;

    float acc[4][4];
#pragma unroll
    for (int i = 0; i < 4; i++)
#pragma unroll
        for (int j = 0; j < 4; j++) acc[i][j] = 0.f;

    for (int kt = 0; kt < Kd; kt += 16) {
        // A tile: 64 rows x 16 k
#pragma unroll
        for (int e = t; e < 1024; e += 256) {
            int m = e >> 4, k = e & 15;
            int gm = bm + m, gk = kt + k;
            As[k][m] = (gm < M && gk < Kd) ? A[(long long)gm * lda + gk] : 0.f;
        }
        // B tile: 16 k x 64 n
        if (!transB) {
#pragma unroll
            for (int e = t; e < 1024; e += 256) {
                int k = e >> 6, n = e & 63;
                int gk = kt + k, gn = bn + n;
                Bs[k][n] = (gk < Kd && gn < Nn) ? B[(long long)gk * ldb + gn] : 0.f;
            }
        } else {
#pragma unroll
            for (int e = t; e < 1024; e += 256) {
                int n = e >> 4, k = e & 15;
                int gk = kt + k, gn = bn + n;
                Bs[k][n] = (gk < Kd && gn < Nn) ? B[(long long)gn * ldb + gk] : 0.f;
            }
        }
        __syncthreads();
#pragma unroll
        for (int k = 0; k < 16; k++) {
            float a[4], b[4];
#pragma unroll
            for (int i = 0; i < 4; i++) a[i] = As[k][ty * 4 + i];
#pragma unroll
            for (int j = 0; j < 4; j++) b[j] = Bs[k][tx * 4 + j];
#pragma unroll
            for (int i = 0; i < 4; i++)
#pragma unroll
                for (int j = 0; j < 4; j++) acc[i][j] += a[i] * b[j];
        }
        __syncthreads();
    }

#pragma unroll
    for (int i = 0; i < 4; i++) {
        int gm = bm + ty * 4 + i;
        if (gm >= M) continue;
#pragma unroll
        for (int j = 0; j < 4; j++) {
            int gn = bn + tx * 4 + j;
            if (gn >= Nn) continue;
            float v = acc[i][j];
            if (epi == 2) {
                v = -2.f * v + sq[gn];
            } else {
                if (bias) v += bias[gn];
                if (epi == 1) v = fmaxf(v, 0.f);
            }
            C[(long long)gm * ldc + gn] = v;
        }
    }
}

// ---------------------------------------------------------------------------
// squared norms, one warp per row
// ---------------------------------------------------------------------------
__global__ void sqnorm_kernel(const float* __restrict__ X, float* __restrict__ sqn, int D)
{
    int warp = (blockIdx.x * blockDim.x + threadIdx.x) >> 5;
    int lane = threadIdx.x & 31;
    if (warp >= NPTS) return;
    const float* row = X + (long long)warp * D;
    float s = 0.f;
    for (int c = lane; c < D; c += 32) { float v = row[c]; s += v * v; }
#pragma unroll
    for (int off = 16; off; off >>= 1) s += __shfl_xor_sync(0xffffffffu, s, off);
    if (lane == 0) sqn[warp] = s;
}

// ---------------------------------------------------------------------------
// top-16 smallest per row (warp per row, 4 rows/block, iterative selection)
// ---------------------------------------------------------------------------
__global__ __launch_bounds__(128)
void topk_kernel(const float* __restrict__ S, int* __restrict__ idx)
{
    __shared__ float sm[4][NN];
    int warp = threadIdx.x >> 5, lane = threadIdx.x & 31;
    int r = blockIdx.x * 4 + warp;
    const float* row = S + (long long)r * NN;
    for (int j = lane; j < NN; j += 32) sm[warp][j] = row[j];
    __syncwarp();

    unsigned long long used = 0ull;
    for (int it = 0; it < KNN; it++) {
        float best = 3.4e38f;
        int bidx = 1 << 30;
#pragma unroll 8
        for (int tt = 0; tt < 64; tt++) {
            if (!((used >> tt) & 1ull)) {
                int j = lane + (tt << 5);
                float v = sm[warp][j];
                if (v < best || (v == best && j < bidx)) { best = v; bidx = j; }
            }
        }
#pragma unroll
        for (int off = 16; off; off >>= 1) {
            float ov = __shfl_xor_sync(0xffffffffu, best, off);
            int oi = __shfl_xor_sync(0xffffffffu, bidx, off);
            if (ov < best || (ov == best && oi < bidx)) { best = ov; bidx = oi; }
        }
        if ((bidx & 31) == lane) used |= 1ull << (bidx >> 5);
        if (lane == 0) idx[r * KNN + it] = bidx;
    }
}

// Wd = W1[:D] - W1[D:2D]
__global__ void wdiff_kernel(const float* __restrict__ W1, float* __restrict__ Wd, int total)
{
    int i = blockIdx.x * blockDim.x + threadIdx.x;
    if (i < total) Wd[i] = W1[i] - W1[total + i];
}

// H1[e] = relu(P[i(e)] + Q[j(e)])   (b1 folded into P)
__global__ void h1_kernel(const float* __restrict__ P, const float* __restrict__ Q,
                          const int* __restrict__ idx, float* __restrict__ H1, int C2)
{
    int e = blockIdx.x;
    int r = e >> 4;
    int b = r >> 11;
    int j = idx[e];
    long long prow = (long long)r * C2;
    long long qrow = (long long)((b << 11) + j) * C2;
    long long hrow = (long long)e * C2;
    for (int c = threadIdx.x; c < C2; c += blockDim.x)
        H1[hrow + c] = fmaxf(P[prow + c] + Q[qrow + c], 0.f);
}

// mean over 16 neighbor rows (outer relu is identity: inputs >= 0)
__global__ void agg_kernel(const float* __restrict__ H2, float* __restrict__ Xout, int Dout)
{
    int r = blockIdx.x;
    for (int c = threadIdx.x; c < Dout; c += blockDim.x) {
        float s = 0.f;
        long long base = ((long long)r * KNN) * Dout + c;
#pragma unroll
        for (int kk = 0; kk < KNN; kk++) s += H2[base + (long long)kk * Dout];
        Xout[(long long)r * Dout + c] = s * (1.f / 16.f);
    }
}

// global mean pool + final linear -> [8,2]
__global__ void final_kernel(const float* __restrict__ X, const float* __restrict__ Wf,
                             const float* __restrict__ bf, float* __restrict__ out)
{
    __shared__ float pooled[BB][16];
    int t = threadIdx.x;
    if (t < 128) {
        int b = t >> 4, c = t & 15;
        float s = 0.f;
        const float* base = X + ((long long)b * NN) * 16 + c;
        for (int n = 0; n < NN; n++) s += base[n * 16];
        pooled[b][c] = s / (float)NN;
    }
    __syncthreads();
    if (t < 16) {
        int b = t >> 1, o = t & 1;
        float s = bf[o];
#pragma unroll
        for (int c = 0; c < 16; c++) s += pooled[b][c] * Wf[c * 2 + o];
        out[b * 2 + o] = s;
    }
}

// ---------------------------------------------------------------------------
extern "C" void kernel_launch(void* const* d_in, const int* in_sizes, int n_in,
                              void* d_out, int out_size)
{
    (void)in_sizes; (void)n_in; (void)out_size;
    static const int DIMS[7] = {3, 32, 128, 256, 64, 32, 16};

    float *X0, *X1, *S, *P, *Q, *Wd, *H1, *H2, *sqn;
    int* idxp;
    cudaGetSymbolAddress((void**)&X0,   g_X0);
    cudaGetSymbolAddress((void**)&X1,   g_X1);
    cudaGetSymbolAddress((void**)&S,    g_S);
    cudaGetSymbolAddress((void**)&P,    g_P);
    cudaGetSymbolAddress((void**)&Q,    g_Q);
    cudaGetSymbolAddress((void**)&Wd,   g_Wd);
    cudaGetSymbolAddress((void**)&H1,   g_H1);
    cudaGetSymbolAddress((void**)&H2,   g_H2);
    cudaGetSymbolAddress((void**)&sqn,  g_sqn);
    cudaGetSymbolAddress((void**)&idxp, g_idx);

    const float* cur = (const float*)d_in[0];

    for (int l = 0; l < 6; l++) {
        int din = DIMS[l], dout = DIMS[l + 1], c2 = 2 * dout;
        const float* W1 = (const float*)d_in[1 + 4 * l];
        const float* b1 = (const float*)d_in[2 + 4 * l];
        const float* W2 = (const float*)d_in[3 + 4 * l];
        const float* b2 = (const float*)d_in[4 + 4 * l];
        float* Xn = (l & 1) ? X1 : X0;

        // 1) squared norms
        sqnorm_kernel<<<NPTS * 32 / 256, 256>>>(cur, sqn, din);

        // 2) distance scores S = -2*X X^T + ||x_j||^2  (batched over B)
        sgemm64<<<dim3(NN / 64, NN / 64, BB), 256>>>(
            cur, cur, nullptr, sqn, S,
            NN, NN, din, din, din, NN,
            /*transB=*/1, /*epi=*/2,
            (long long)NN * din, (long long)NN * din, (long long)NN * NN, NN);

        // 3) top-16 neighbor indices
        topk_kernel<<<NPTS / 4, 128>>>(S, idxp);

        // 4) Wd = W1a - W1b
        wdiff_kernel<<<(din * c2 + 255) / 256, 256>>>(W1, Wd, din * c2);

        // 5) P = X @ Wd + b1 ;  Q = X @ W1b
        sgemm64<<<dim3((c2 + 63) / 64, NPTS / 64, 1), 256>>>(
            cur, Wd, b1, nullptr, P,
            NPTS, c2, din, din, c2, c2, 0, 0, 0, 0, 0, 0);
        sgemm64<<<dim3((c2 + 63) / 64, NPTS / 64, 1), 256>>>(
            cur, W1 + (long long)din * c2, nullptr, nullptr, Q,
            NPTS, c2, din, din, c2, c2, 0, 0, 0, 0, 0, 0);

        // 6) H1[e] = relu(P_i + Q_j)
        h1_kernel<<<NEDGE, 256>>>(P, Q, idxp, H1, c2);

        // 7) H2 = relu(H1 @ W2 + b2)
        sgemm64<<<dim3((dout + 63) / 64, NEDGE / 64, 1), 256>>>(
            H1, W2, b2, nullptr, H2,
            NEDGE, dout, c2, c2, dout, dout, 0, 1, 0, 0, 0, 0);

        // 8) mean over k neighbors -> next layer features
        agg_kernel<<<NPTS, 256>>>(H2, Xn, dout);

        cur = Xn;
    }

    final_kernel<<<1, 128>>>(cur, (const float*)d_in[25], (const float*)d_in[26],
                             (float*)d_out);
}